// round 1
// baseline (speedup 1.0000x reference)
#include <cuda_runtime.h>
#include <math.h>

#define MT   4096    // B*T rows
#define DM   1024
#define DFF  4096

// ---------------- scratch (device globals; no allocation allowed) -----------
__device__ float g_xn[MT * DM];     // rmsnorm output (reused for both norms)
__device__ float g_q[MT * DM];
__device__ float g_k[MT * DM];
__device__ float g_v[MT * DM];
__device__ float g_attn[MT * DM];   // attention output (pre O-proj)
__device__ float g_x1[MT * DM];     // x + attn
__device__ float g_h[MT * DFF];     // ffn hidden

// ---------------- rmsnorm ----------------
__global__ void rmsnorm_kernel(const float* __restrict__ x,
                               const float* __restrict__ w,
                               float* __restrict__ out) {
    int row = blockIdx.x;
    int tid = threadIdx.x;  // 256 threads, 4 floats each
    const float4* x4 = reinterpret_cast<const float4*>(x + (size_t)row * DM);
    const float4* w4 = reinterpret_cast<const float4*>(w);
    float4* o4 = reinterpret_cast<float4*>(out + (size_t)row * DM);
    float4 v = x4[tid];
    float ss = v.x * v.x + v.y * v.y + v.z * v.z + v.w * v.w;
#pragma unroll
    for (int off = 16; off; off >>= 1)
        ss += __shfl_xor_sync(0xffffffffu, ss, off);
    __shared__ float sred[8];
    __shared__ float stot;
    if ((tid & 31) == 0) sred[tid >> 5] = ss;
    __syncthreads();
    if (tid == 0) {
        float t = 0.f;
#pragma unroll
        for (int i = 0; i < 8; i++) t += sred[i];
        stot = rsqrtf(t * (1.0f / DM) + 1e-5f);
    }
    __syncthreads();
    float rinv = stot;
    float4 wv = w4[tid];
    float4 r;
    r.x = wv.x * v.x * rinv;
    r.y = wv.y * v.y * rinv;
    r.z = wv.z * v.z * rinv;
    r.w = wv.w * v.w * rinv;
    o4[tid] = r;
}

// ---------------- GEMM: C[m,n] = sum_k A[m,k] * B[n,k] (+epilogue) ----------
#define GM_NONE 0
#define GM_GELU 1
#define GM_RES  2

__device__ __forceinline__ float gelu_exact(float x) {
    return 0.5f * x * (1.0f + erff(x * 0.70710678118654752f));
}

template <int MODE>
__global__ __launch_bounds__(256)
void sgemm_nt(const float* __restrict__ A, const float* __restrict__ B,
              const float* __restrict__ Res, float* __restrict__ C,
              int M, int N, int K) {
    __shared__ float As[8][128];
    __shared__ float Bs[8][128];
    int tid = threadIdx.x;
    int m0 = blockIdx.y * 128;
    int n0 = blockIdx.x * 128;
    int lrow = tid >> 1;          // 0..127
    int lk4  = (tid & 1) * 4;     // 0 or 4
    int tx = tid & 15;            // 0..15
    int ty = tid >> 4;            // 0..15

    float acc[8][8];
#pragma unroll
    for (int i = 0; i < 8; i++)
#pragma unroll
        for (int j = 0; j < 8; j++) acc[i][j] = 0.f;

    const float* Aptr = A + (size_t)(m0 + lrow) * K + lk4;
    const float* Bptr = B + (size_t)(n0 + lrow) * K + lk4;

    for (int kt = 0; kt < K; kt += 8) {
        float4 av = *reinterpret_cast<const float4*>(Aptr + kt);
        float4 bv = *reinterpret_cast<const float4*>(Bptr + kt);
        As[lk4 + 0][lrow] = av.x;
        As[lk4 + 1][lrow] = av.y;
        As[lk4 + 2][lrow] = av.z;
        As[lk4 + 3][lrow] = av.w;
        Bs[lk4 + 0][lrow] = bv.x;
        Bs[lk4 + 1][lrow] = bv.y;
        Bs[lk4 + 2][lrow] = bv.z;
        Bs[lk4 + 3][lrow] = bv.w;
        __syncthreads();
#pragma unroll
        for (int kk = 0; kk < 8; kk++) {
            float4 a0 = *reinterpret_cast<const float4*>(&As[kk][ty * 4]);
            float4 a1 = *reinterpret_cast<const float4*>(&As[kk][64 + ty * 4]);
            float4 b0 = *reinterpret_cast<const float4*>(&Bs[kk][tx * 4]);
            float4 b1 = *reinterpret_cast<const float4*>(&Bs[kk][64 + tx * 4]);
            float ar[8] = {a0.x, a0.y, a0.z, a0.w, a1.x, a1.y, a1.z, a1.w};
            float br[8] = {b0.x, b0.y, b0.z, b0.w, b1.x, b1.y, b1.z, b1.w};
#pragma unroll
            for (int i = 0; i < 8; i++)
#pragma unroll
                for (int j = 0; j < 8; j++) acc[i][j] += ar[i] * br[j];
        }
        __syncthreads();
    }

    // epilogue
#pragma unroll
    for (int i = 0; i < 8; i++) {
        int m = m0 + ((i < 4) ? (ty * 4 + i) : (64 + ty * 4 + (i - 4)));
#pragma unroll
        for (int half = 0; half < 2; half++) {
            int n = n0 + ((half == 0) ? (tx * 4) : (64 + tx * 4));
            float4 vo;
            vo.x = acc[i][half * 4 + 0];
            vo.y = acc[i][half * 4 + 1];
            vo.z = acc[i][half * 4 + 2];
            vo.w = acc[i][half * 4 + 3];
            if (MODE == GM_GELU) {
                vo.x = gelu_exact(vo.x);
                vo.y = gelu_exact(vo.y);
                vo.z = gelu_exact(vo.z);
                vo.w = gelu_exact(vo.w);
            }
            if (MODE == GM_RES) {
                float4 rv = *reinterpret_cast<const float4*>(Res + (size_t)m * N + n);
                vo.x += rv.x; vo.y += rv.y; vo.z += rv.z; vo.w += rv.w;
            }
            *reinterpret_cast<float4*>(C + (size_t)m * N + n) = vo;
        }
    }
}

// ---------------- flash attention (fp32, causal) ----------------
// Grid: (32 q-blocks, 16 heads, 2 batch). 128 threads.
// Bq=64 queries, Bk=32 keys per inner block, dk=64.
__global__ __launch_bounds__(128)
void attn_kernel(const float* __restrict__ q, const float* __restrict__ k,
                 const float* __restrict__ v, float* __restrict__ o) {
    __shared__ float Qs[64][68];
    __shared__ float Ks[32][68];
    __shared__ float Vs[32][68];
    __shared__ float Ps[64][36];

    int qb = blockIdx.x;
    int h  = blockIdx.y;
    int b  = blockIdx.z;
    int tid = threadIdx.x;
    int row0 = b * 2048;
    int col0 = h * 64;

    // Load Q block (64x64), pre-scaled by 1/sqrt(dk)=0.125
#pragma unroll
    for (int it = 0; it < 8; it++) {
        int idx = it * 128 + tid;
        int r = idx >> 4;
        int c4 = (idx & 15) * 4;
        float4 val = *reinterpret_cast<const float4*>(
            q + (size_t)(row0 + qb * 64 + r) * DM + col0 + c4);
        val.x *= 0.125f; val.y *= 0.125f; val.z *= 0.125f; val.w *= 0.125f;
        *reinterpret_cast<float4*>(&Qs[r][c4]) = val;
    }

    int tx = tid & 7;    // 0..7  -> score cols tx*4.., out cols tx*8..
    int ty = tid >> 3;   // 0..15 -> rows ty*4..

    float m_i[4], l_i[4], acc[4][8];
#pragma unroll
    for (int i = 0; i < 4; i++) {
        m_i[i] = -1e30f;
        l_i[i] = 0.f;
#pragma unroll
        for (int j = 0; j < 8; j++) acc[i][j] = 0.f;
    }

    int nkb = 2 * qb + 2;  // key blocks of 32 covering keys [0, (qb+1)*64)
    for (int jb = 0; jb < nkb; jb++) {
        __syncthreads();  // protect Ks/Vs/Ps from previous iteration readers
#pragma unroll
        for (int it = 0; it < 4; it++) {
            int idx = it * 128 + tid;
            int r = idx >> 4;
            int c4 = (idx & 15) * 4;
            size_t gi = (size_t)(row0 + jb * 32 + r) * DM + col0 + c4;
            *reinterpret_cast<float4*>(&Ks[r][c4]) =
                *reinterpret_cast<const float4*>(k + gi);
            *reinterpret_cast<float4*>(&Vs[r][c4]) =
                *reinterpret_cast<const float4*>(v + gi);
        }
        __syncthreads();

        // S = (Q*scale) K^T : per-thread 4x4
        float s[4][4];
#pragma unroll
        for (int i = 0; i < 4; i++)
#pragma unroll
            for (int j = 0; j < 4; j++) s[i][j] = 0.f;

#pragma unroll
        for (int kk = 0; kk < 64; kk += 4) {
            float4 qv[4], kv[4];
#pragma unroll
            for (int i = 0; i < 4; i++)
                qv[i] = *reinterpret_cast<const float4*>(&Qs[ty * 4 + i][kk]);
#pragma unroll
            for (int j = 0; j < 4; j++)
                kv[j] = *reinterpret_cast<const float4*>(&Ks[tx * 4 + j][kk]);
#pragma unroll
            for (int i = 0; i < 4; i++)
#pragma unroll
                for (int j = 0; j < 4; j++)
                    s[i][j] += qv[i].x * kv[j].x + qv[i].y * kv[j].y +
                               qv[i].z * kv[j].z + qv[i].w * kv[j].w;
        }

        if (jb >= 2 * qb) {  // only the two diagonal-straddling blocks need mask
#pragma unroll
            for (int i = 0; i < 4; i++)
#pragma unroll
                for (int j = 0; j < 4; j++)
                    if (jb * 32 + tx * 4 + j > qb * 64 + ty * 4 + i)
                        s[i][j] = -1e30f;
        }

        // online softmax (rows replicated across the 8 tx lanes of each group)
#pragma unroll
        for (int i = 0; i < 4; i++) {
            float mx = fmaxf(fmaxf(s[i][0], s[i][1]), fmaxf(s[i][2], s[i][3]));
            mx = fmaxf(mx, __shfl_xor_sync(0xffffffffu, mx, 1));
            mx = fmaxf(mx, __shfl_xor_sync(0xffffffffu, mx, 2));
            mx = fmaxf(mx, __shfl_xor_sync(0xffffffffu, mx, 4));
            float mnew = fmaxf(m_i[i], mx);
            float sc = __expf(m_i[i] - mnew);
            float p0 = __expf(s[i][0] - mnew);
            float p1 = __expf(s[i][1] - mnew);
            float p2 = __expf(s[i][2] - mnew);
            float p3 = __expf(s[i][3] - mnew);
            float rs = p0 + p1 + p2 + p3;
            rs += __shfl_xor_sync(0xffffffffu, rs, 1);
            rs += __shfl_xor_sync(0xffffffffu, rs, 2);
            rs += __shfl_xor_sync(0xffffffffu, rs, 4);
            l_i[i] = l_i[i] * sc + rs;
            m_i[i] = mnew;
#pragma unroll
            for (int j = 0; j < 8; j++) acc[i][j] *= sc;
            Ps[ty * 4 + i][tx * 4 + 0] = p0;
            Ps[ty * 4 + i][tx * 4 + 1] = p1;
            Ps[ty * 4 + i][tx * 4 + 2] = p2;
            Ps[ty * 4 + i][tx * 4 + 3] = p3;
        }
        __syncthreads();

        // O += P V : out cols tx*8 .. tx*8+7
#pragma unroll
        for (int c = 0; c < 32; c++) {
            float4 v0 = *reinterpret_cast<const float4*>(&Vs[c][tx * 8]);
            float4 v1 = *reinterpret_cast<const float4*>(&Vs[c][tx * 8 + 4]);
#pragma unroll
            for (int i = 0; i < 4; i++) {
                float p = Ps[ty * 4 + i][c];
                acc[i][0] += p * v0.x;
                acc[i][1] += p * v0.y;
                acc[i][2] += p * v0.z;
                acc[i][3] += p * v0.w;
                acc[i][4] += p * v1.x;
                acc[i][5] += p * v1.y;
                acc[i][6] += p * v1.z;
                acc[i][7] += p * v1.w;
            }
        }
    }

    // write normalized output
#pragma unroll
    for (int i = 0; i < 4; i++) {
        float inv = 1.0f / l_i[i];
        float4 o0, o1;
        o0.x = acc[i][0] * inv; o0.y = acc[i][1] * inv;
        o0.z = acc[i][2] * inv; o0.w = acc[i][3] * inv;
        o1.x = acc[i][4] * inv; o1.y = acc[i][5] * inv;
        o1.z = acc[i][6] * inv; o1.w = acc[i][7] * inv;
        size_t base = (size_t)(row0 + qb * 64 + ty * 4 + i) * DM + col0 + tx * 8;
        *reinterpret_cast<float4*>(o + base) = o0;
        *reinterpret_cast<float4*>(o + base + 4) = o1;
    }
}

// ---------------- launch ----------------
extern "C" void kernel_launch(void* const* d_in, const int* in_sizes, int n_in,
                              void* d_out, int out_size) {
    const float* x     = (const float*)d_in[0];
    const float* wq    = (const float*)d_in[1];
    const float* wk    = (const float*)d_in[2];
    const float* wv    = (const float*)d_in[3];
    const float* wo    = (const float*)d_in[4];
    const float* ln1_w = (const float*)d_in[5];
    const float* ln2_w = (const float*)d_in[6];
    const float* w1    = (const float*)d_in[7];
    const float* w2    = (const float*)d_in[8];
    float* out = (float*)d_out;

    float *p_xn, *p_q, *p_k, *p_v, *p_attn, *p_x1, *p_h;
    cudaGetSymbolAddress((void**)&p_xn, g_xn);
    cudaGetSymbolAddress((void**)&p_q, g_q);
    cudaGetSymbolAddress((void**)&p_k, g_k);
    cudaGetSymbolAddress((void**)&p_v, g_v);
    cudaGetSymbolAddress((void**)&p_attn, g_attn);
    cudaGetSymbolAddress((void**)&p_x1, g_x1);
    cudaGetSymbolAddress((void**)&p_h, g_h);

    dim3 gemm_d1024(DM / 128, MT / 128);    // N=1024
    dim3 gemm_dff(DFF / 128, MT / 128);     // N=4096

    // 1. xn1 = rmsnorm(x, ln1_w)
    rmsnorm_kernel<<<MT, 256>>>(x, ln1_w, p_xn);

    // 2. Q, K, V = xn1 @ {wq,wk,wv}.T
    sgemm_nt<GM_NONE><<<gemm_d1024, 256>>>(p_xn, wq, nullptr, p_q, MT, DM, DM);
    sgemm_nt<GM_NONE><<<gemm_d1024, 256>>>(p_xn, wk, nullptr, p_k, MT, DM, DM);
    sgemm_nt<GM_NONE><<<gemm_d1024, 256>>>(p_xn, wv, nullptr, p_v, MT, DM, DM);

    // 3. causal flash attention
    attn_kernel<<<dim3(32, 16, 2), 128>>>(p_q, p_k, p_v, p_attn);

    // 4. x1 = x + attn @ wo.T
    sgemm_nt<GM_RES><<<gemm_d1024, 256>>>(p_attn, wo, x, p_x1, MT, DM, DM);

    // 5. xn2 = rmsnorm(x1, ln2_w)
    rmsnorm_kernel<<<MT, 256>>>(p_x1, ln2_w, p_xn);

    // 6. h = gelu(xn2 @ w1.T)
    sgemm_nt<GM_GELU><<<gemm_dff, 256>>>(p_xn, w1, nullptr, p_h, MT, DFF, DM);

    // 7. out = x1 + h @ w2.T
    sgemm_nt<GM_RES><<<gemm_d1024, 256>>>(p_h, w2, p_x1, out, MT, DM, DFF);
}

// round 3
// speedup vs baseline: 1.5979x; 1.5979x over previous
#include <cuda_runtime.h>
#include <math.h>
#include <stdint.h>

#define MT   4096    // B*T rows
#define DM   1024
#define DFF  4096

// ---------------- scratch (device globals; no allocation allowed) -----------
__device__ float g_xn[MT * DM];
__device__ float g_q[MT * DM];
__device__ float g_k[MT * DM];
__device__ float g_v[MT * DM];
__device__ float g_attn[MT * DM];
__device__ float g_x1[MT * DM];
__device__ float g_h[MT * DFF];

// ---------------- helpers ----------------
__device__ __forceinline__ uint32_t tf32rna(uint32_t xbits) {
    uint32_t r;
    float xf = __uint_as_float(xbits);
    asm("cvt.rna.tf32.f32 %0, %1;" : "=r"(r) : "f"(xf));
    return r;
}

__device__ __forceinline__ void mma_tf32(float c[4], uint32_t a0, uint32_t a1,
                                         uint32_t a2, uint32_t a3,
                                         uint32_t b0, uint32_t b1) {
    asm volatile(
        "mma.sync.aligned.m16n8k8.row.col.f32.tf32.tf32.f32 "
        "{%0,%1,%2,%3}, {%4,%5,%6,%7}, {%8,%9}, {%0,%1,%2,%3};"
        : "+f"(c[0]), "+f"(c[1]), "+f"(c[2]), "+f"(c[3])
        : "r"(a0), "r"(a1), "r"(a2), "r"(a3), "r"(b0), "r"(b1));
}

__device__ __forceinline__ float gelu_exact(float x) {
    return 0.5f * x * (1.0f + erff(x * 0.70710678118654752f));
}

#define GM_NONE 0
#define GM_GELU 1
#define GM_RES  2

// ============================================================================
// tf32 tensor-core GEMM: C[m,n] = sum_k A[m,k] * B[n,k]  (+ epilogue)
// CTA tile 128x128x16, 8 warps (2 M x 4 N), warp tile 64x32 (4x4 m16n8k8).
// Smem holds tiles in FRAGMENT ORDER so fragment fetch = 1 vector LDS.
//
// A frag layout (per m16n8k8 tile tm, k-step s):
//   element (m,k): r = ((k&7)>>2)*2 + ((m&15)>>3), lane = (m&7)*4 + (k&3)
//   offset = ((tm*2+s)*32 + lane)*16 + r*4          (A buffer: 8*2*32*16 = 8KB)
// B frag layout (per n-tile tn of 8, k-step s):
//   element (n,k): r = (k&7)>>2, lane = (n&7)*4 + (k&3)
//   offset = ((tn*2+s)*32 + lane)*8 + r*4           (B buffer: 16*2*32*8 = 8KB)
// ============================================================================
template <int MODE>
__global__ __launch_bounds__(256)
void gemm_tc(const float* __restrict__ A, const float* __restrict__ B,
             const float* __restrict__ Res, float* __restrict__ C,
             int M, int N, int K) {
    __shared__ __align__(16) char smA[2][8192];
    __shared__ __align__(16) char smB[2][8192];

    int tid = threadIdx.x;
    int wid = tid >> 5;
    int lane = tid & 31;
    int wm = wid >> 2;           // 0..1
    int wn = wid & 3;            // 0..3
    int g  = lane >> 2;          // group id 0..7
    int t4 = lane & 3;           // thread in group

    int m0 = blockIdx.y * 128;
    int n0 = blockIdx.x * 128;

    // ---- staging coordinates (thread-constant) ----
    int arow[2], ac4[2];
    uint32_t aoff[2][4], boff[2][4];
#pragma unroll
    for (int q = 0; q < 2; q++) {
        int id = q * 256 + tid;
        int row = id >> 2;       // 0..127
        int c4  = id & 3;        // float4 index within 16-float k-row
        arow[q] = row; ac4[q] = c4;
        int s  = c4 >> 1;
        int kh = c4 & 1;
#pragma unroll
        for (int j = 0; j < 4; j++) {
            int ln = (row & 7) * 4 + j;
            // A offsets
            int tm = row >> 4;
            int r  = kh * 2 + ((row & 15) >> 3);
            aoff[q][j] = ((tm * 2 + s) * 32 + ln) * 16 + r * 4;
            // B offsets
            int tn = row >> 3;
            boff[q][j] = ((tn * 2 + s) * 32 + ln) * 8 + kh * 4;
        }
    }

    const float* Ag = A + (size_t)m0 * K;
    const float* Bg = B + (size_t)n0 * K;

    float acc[4][4][4];
#pragma unroll
    for (int i = 0; i < 4; i++)
#pragma unroll
        for (int j = 0; j < 4; j++)
#pragma unroll
            for (int r = 0; r < 4; r++) acc[i][j][r] = 0.f;

    int NT = K >> 4;  // k-tiles of 16

    uint4 ra[2], rb[2];
    // prefetch tile 0
#pragma unroll
    for (int q = 0; q < 2; q++) {
        ra[q] = *reinterpret_cast<const uint4*>(Ag + (size_t)arow[q] * K + ac4[q] * 4);
        rb[q] = *reinterpret_cast<const uint4*>(Bg + (size_t)arow[q] * K + ac4[q] * 4);
    }
    // store tile 0 into buf 0 (tf32 rna)
#pragma unroll
    for (int q = 0; q < 2; q++) {
        uint32_t av[4] = {ra[q].x, ra[q].y, ra[q].z, ra[q].w};
        uint32_t bv[4] = {rb[q].x, rb[q].y, rb[q].z, rb[q].w};
#pragma unroll
        for (int j = 0; j < 4; j++) {
            *reinterpret_cast<uint32_t*>(smA[0] + aoff[q][j]) = tf32rna(av[j]);
            *reinterpret_cast<uint32_t*>(smB[0] + boff[q][j]) = tf32rna(bv[j]);
        }
    }
    __syncthreads();

    for (int t = 0; t < NT; t++) {
        int buf = t & 1;
        // prefetch next tile global -> regs
        if (t + 1 < NT) {
            int k0 = (t + 1) * 16;
#pragma unroll
            for (int q = 0; q < 2; q++) {
                ra[q] = *reinterpret_cast<const uint4*>(Ag + (size_t)arow[q] * K + k0 + ac4[q] * 4);
                rb[q] = *reinterpret_cast<const uint4*>(Bg + (size_t)arow[q] * K + k0 + ac4[q] * 4);
            }
        }

        // compute 2 k-steps on buf
#pragma unroll
        for (int s = 0; s < 2; s++) {
            uint4 af[4];
            uint2 bf[4];
#pragma unroll
            for (int i = 0; i < 4; i++) {
                int tm = wm * 4 + i;
                af[i] = *reinterpret_cast<const uint4*>(
                    smA[buf] + ((tm * 2 + s) * 32 + lane) * 16);
            }
#pragma unroll
            for (int j = 0; j < 4; j++) {
                int tn = wn * 4 + j;
                bf[j] = *reinterpret_cast<const uint2*>(
                    smB[buf] + ((tn * 2 + s) * 32 + lane) * 8);
            }
#pragma unroll
            for (int i = 0; i < 4; i++)
#pragma unroll
                for (int j = 0; j < 4; j++)
                    mma_tf32(acc[i][j], af[i].x, af[i].y, af[i].z, af[i].w,
                             bf[j].x, bf[j].y);
        }

        // store prefetched tile into the other buffer
        if (t + 1 < NT) {
#pragma unroll
            for (int q = 0; q < 2; q++) {
                uint32_t av[4] = {ra[q].x, ra[q].y, ra[q].z, ra[q].w};
                uint32_t bv[4] = {rb[q].x, rb[q].y, rb[q].z, rb[q].w};
#pragma unroll
                for (int j = 0; j < 4; j++) {
                    *reinterpret_cast<uint32_t*>(smA[buf ^ 1] + aoff[q][j]) = tf32rna(av[j]);
                    *reinterpret_cast<uint32_t*>(smB[buf ^ 1] + boff[q][j]) = tf32rna(bv[j]);
                }
            }
        }
        __syncthreads();
    }

    // ---- epilogue ----
#pragma unroll
    for (int i = 0; i < 4; i++) {
#pragma unroll
        for (int j = 0; j < 4; j++) {
            int mlo = m0 + wm * 64 + i * 16 + g;
            int n   = n0 + wn * 32 + j * 8 + t4 * 2;
            float2 v0 = make_float2(acc[i][j][0], acc[i][j][1]);
            float2 v1 = make_float2(acc[i][j][2], acc[i][j][3]);
            if (MODE == GM_GELU) {
                v0.x = gelu_exact(v0.x); v0.y = gelu_exact(v0.y);
                v1.x = gelu_exact(v1.x); v1.y = gelu_exact(v1.y);
            }
            if (MODE == GM_RES) {
                float2 r0 = *reinterpret_cast<const float2*>(Res + (size_t)mlo * N + n);
                float2 r1 = *reinterpret_cast<const float2*>(Res + (size_t)(mlo + 8) * N + n);
                v0.x += r0.x; v0.y += r0.y;
                v1.x += r1.x; v1.y += r1.y;
            }
            *reinterpret_cast<float2*>(C + (size_t)mlo * N + n) = v0;
            *reinterpret_cast<float2*>(C + (size_t)(mlo + 8) * N + n) = v1;
        }
    }
}

// ---------------- rmsnorm ----------------
__global__ void rmsnorm_kernel(const float* __restrict__ x,
                               const float* __restrict__ w,
                               float* __restrict__ out) {
    int row = blockIdx.x;
    int tid = threadIdx.x;
    const float4* x4 = reinterpret_cast<const float4*>(x + (size_t)row * DM);
    const float4* w4 = reinterpret_cast<const float4*>(w);
    float4* o4 = reinterpret_cast<float4*>(out + (size_t)row * DM);
    float4 v = x4[tid];
    float ss = v.x * v.x + v.y * v.y + v.z * v.z + v.w * v.w;
#pragma unroll
    for (int off = 16; off; off >>= 1)
        ss += __shfl_xor_sync(0xffffffffu, ss, off);
    __shared__ float sred[8];
    __shared__ float stot;
    if ((tid & 31) == 0) sred[tid >> 5] = ss;
    __syncthreads();
    if (tid == 0) {
        float t = 0.f;
#pragma unroll
        for (int i = 0; i < 8; i++) t += sred[i];
        stot = rsqrtf(t * (1.0f / DM) + 1e-5f);
    }
    __syncthreads();
    float rinv = stot;
    float4 wv = w4[tid];
    float4 r;
    r.x = wv.x * v.x * rinv;
    r.y = wv.y * v.y * rinv;
    r.z = wv.z * v.z * rinv;
    r.w = wv.w * v.w * rinv;
    o4[tid] = r;
}

// ---------------- flash attention (fp32, causal) ----------------
__global__ __launch_bounds__(128)
void attn_kernel(const float* __restrict__ q, const float* __restrict__ k,
                 const float* __restrict__ v, float* __restrict__ o) {
    __shared__ float Qs[64][68];
    __shared__ float Ks[32][68];
    __shared__ float Vs[32][68];
    __shared__ float Ps[64][36];

    int qb = blockIdx.x;
    int h  = blockIdx.y;
    int b  = blockIdx.z;
    int tid = threadIdx.x;
    int row0 = b * 2048;
    int col0 = h * 64;

#pragma unroll
    for (int it = 0; it < 8; it++) {
        int idx = it * 128 + tid;
        int r = idx >> 4;
        int c4 = (idx & 15) * 4;
        float4 val = *reinterpret_cast<const float4*>(
            q + (size_t)(row0 + qb * 64 + r) * DM + col0 + c4);
        val.x *= 0.125f; val.y *= 0.125f; val.z *= 0.125f; val.w *= 0.125f;
        *reinterpret_cast<float4*>(&Qs[r][c4]) = val;
    }

    int tx = tid & 7;
    int ty = tid >> 3;

    float m_i[4], l_i[4], acc[4][8];
#pragma unroll
    for (int i = 0; i < 4; i++) {
        m_i[i] = -1e30f;
        l_i[i] = 0.f;
#pragma unroll
        for (int j = 0; j < 8; j++) acc[i][j] = 0.f;
    }

    int nkb = 2 * qb + 2;
    for (int jb = 0; jb < nkb; jb++) {
        __syncthreads();
#pragma unroll
        for (int it = 0; it < 4; it++) {
            int idx = it * 128 + tid;
            int r = idx >> 4;
            int c4 = (idx & 15) * 4;
            size_t gi = (size_t)(row0 + jb * 32 + r) * DM + col0 + c4;
            *reinterpret_cast<float4*>(&Ks[r][c4]) =
                *reinterpret_cast<const float4*>(k + gi);
            *reinterpret_cast<float4*>(&Vs[r][c4]) =
                *reinterpret_cast<const float4*>(v + gi);
        }
        __syncthreads();

        float s[4][4];
#pragma unroll
        for (int i = 0; i < 4; i++)
#pragma unroll
            for (int j = 0; j < 4; j++) s[i][j] = 0.f;

#pragma unroll
        for (int kk = 0; kk < 64; kk += 4) {
            float4 qv[4], kv[4];
#pragma unroll
            for (int i = 0; i < 4; i++)
                qv[i] = *reinterpret_cast<const float4*>(&Qs[ty * 4 + i][kk]);
#pragma unroll
            for (int j = 0; j < 4; j++)
                kv[j] = *reinterpret_cast<const float4*>(&Ks[tx * 4 + j][kk]);
#pragma unroll
            for (int i = 0; i < 4; i++)
#pragma unroll
                for (int j = 0; j < 4; j++)
                    s[i][j] += qv[i].x * kv[j].x + qv[i].y * kv[j].y +
                               qv[i].z * kv[j].z + qv[i].w * kv[j].w;
        }

        if (jb >= 2 * qb) {
#pragma unroll
            for (int i = 0; i < 4; i++)
#pragma unroll
                for (int j = 0; j < 4; j++)
                    if (jb * 32 + tx * 4 + j > qb * 64 + ty * 4 + i)
                        s[i][j] = -1e30f;
        }

#pragma unroll
        for (int i = 0; i < 4; i++) {
            float mx = fmaxf(fmaxf(s[i][0], s[i][1]), fmaxf(s[i][2], s[i][3]));
            mx = fmaxf(mx, __shfl_xor_sync(0xffffffffu, mx, 1));
            mx = fmaxf(mx, __shfl_xor_sync(0xffffffffu, mx, 2));
            mx = fmaxf(mx, __shfl_xor_sync(0xffffffffu, mx, 4));
            float mnew = fmaxf(m_i[i], mx);
            float sc = __expf(m_i[i] - mnew);
            float p0 = __expf(s[i][0] - mnew);
            float p1 = __expf(s[i][1] - mnew);
            float p2 = __expf(s[i][2] - mnew);
            float p3 = __expf(s[i][3] - mnew);
            float rs = p0 + p1 + p2 + p3;
            rs += __shfl_xor_sync(0xffffffffu, rs, 1);
            rs += __shfl_xor_sync(0xffffffffu, rs, 2);
            rs += __shfl_xor_sync(0xffffffffu, rs, 4);
            l_i[i] = l_i[i] * sc + rs;
            m_i[i] = mnew;
#pragma unroll
            for (int j = 0; j < 8; j++) acc[i][j] *= sc;
            Ps[ty * 4 + i][tx * 4 + 0] = p0;
            Ps[ty * 4 + i][tx * 4 + 1] = p1;
            Ps[ty * 4 + i][tx * 4 + 2] = p2;
            Ps[ty * 4 + i][tx * 4 + 3] = p3;
        }
        __syncthreads();

#pragma unroll
        for (int c = 0; c < 32; c++) {
            float4 v0 = *reinterpret_cast<const float4*>(&Vs[c][tx * 8]);
            float4 v1 = *reinterpret_cast<const float4*>(&Vs[c][tx * 8 + 4]);
#pragma unroll
            for (int i = 0; i < 4; i++) {
                float p = Ps[ty * 4 + i][c];
                acc[i][0] += p * v0.x;
                acc[i][1] += p * v0.y;
                acc[i][2] += p * v0.z;
                acc[i][3] += p * v0.w;
                acc[i][4] += p * v1.x;
                acc[i][5] += p * v1.y;
                acc[i][6] += p * v1.z;
                acc[i][7] += p * v1.w;
            }
        }
    }

#pragma unroll
    for (int i = 0; i < 4; i++) {
        float inv = 1.0f / l_i[i];
        float4 o0, o1;
        o0.x = acc[i][0] * inv; o0.y = acc[i][1] * inv;
        o0.z = acc[i][2] * inv; o0.w = acc[i][3] * inv;
        o1.x = acc[i][4] * inv; o1.y = acc[i][5] * inv;
        o1.z = acc[i][6] * inv; o1.w = acc[i][7] * inv;
        size_t base = (size_t)(row0 + qb * 64 + ty * 4 + i) * DM + col0 + tx * 8;
        *reinterpret_cast<float4*>(o + base) = o0;
        *reinterpret_cast<float4*>(o + base + 4) = o1;
    }
}

// ---------------- launch ----------------
extern "C" void kernel_launch(void* const* d_in, const int* in_sizes, int n_in,
                              void* d_out, int out_size) {
    const float* x     = (const float*)d_in[0];
    const float* wq    = (const float*)d_in[1];
    const float* wk    = (const float*)d_in[2];
    const float* wv    = (const float*)d_in[3];
    const float* wo    = (const float*)d_in[4];
    const float* ln1_w = (const float*)d_in[5];
    const float* ln2_w = (const float*)d_in[6];
    const float* w1    = (const float*)d_in[7];
    const float* w2    = (const float*)d_in[8];
    float* out = (float*)d_out;

    float *p_xn, *p_q, *p_k, *p_v, *p_attn, *p_x1, *p_h;
    cudaGetSymbolAddress((void**)&p_xn, g_xn);
    cudaGetSymbolAddress((void**)&p_q, g_q);
    cudaGetSymbolAddress((void**)&p_k, g_k);
    cudaGetSymbolAddress((void**)&p_v, g_v);
    cudaGetSymbolAddress((void**)&p_attn, g_attn);
    cudaGetSymbolAddress((void**)&p_x1, g_x1);
    cudaGetSymbolAddress((void**)&p_h, g_h);

    dim3 gd_1024(DM / 128, MT / 128);   // 8 x 32
    dim3 gd_ff(DFF / 128, MT / 128);    // 32 x 32

    // 1. xn1 = rmsnorm(x, ln1_w)
    rmsnorm_kernel<<<MT, 256>>>(x, ln1_w, p_xn);

    // 2. Q, K, V
    gemm_tc<GM_NONE><<<gd_1024, 256>>>(p_xn, wq, nullptr, p_q, MT, DM, DM);
    gemm_tc<GM_NONE><<<gd_1024, 256>>>(p_xn, wk, nullptr, p_k, MT, DM, DM);
    gemm_tc<GM_NONE><<<gd_1024, 256>>>(p_xn, wv, nullptr, p_v, MT, DM, DM);

    // 3. causal flash attention
    attn_kernel<<<dim3(32, 16, 2), 128>>>(p_q, p_k, p_v, p_attn);

    // 4. x1 = x + attn @ wo.T
    gemm_tc<GM_RES><<<gd_1024, 256>>>(p_attn, wo, x, p_x1, MT, DM, DM);

    // 5. xn2 = rmsnorm(x1, ln2_w)
    rmsnorm_kernel<<<MT, 256>>>(p_x1, ln2_w, p_xn);

    // 6. h = gelu(xn2 @ w1.T)
    gemm_tc<GM_GELU><<<gd_ff, 256>>>(p_xn, w1, nullptr, p_h, MT, DFF, DM);

    // 7. out = x1 + h @ w2.T
    gemm_tc<GM_RES><<<gd_1024, 256>>>(p_h, w2, p_x1, out, MT, DM, DFF);
}

// round 4
// speedup vs baseline: 2.6998x; 1.6896x over previous
#include <cuda_runtime.h>
#include <math.h>
#include <stdint.h>

#define MT   4096    // B*T rows
#define DM   1024
#define DFF  4096

// ---------------- scratch (device globals; no allocation allowed) -----------
__device__ float g_xn[MT * DM];
__device__ float g_q[MT * DM];
__device__ float g_k[MT * DM];
__device__ float g_v[MT * DM];
__device__ float g_attn[MT * DM];
__device__ float g_x1[MT * DM];
__device__ float g_h[MT * DFF];

// ---------------- helpers ----------------
__device__ __forceinline__ uint32_t tf32rna_u(uint32_t xbits) {
    uint32_t r;
    float xf = __uint_as_float(xbits);
    asm("cvt.rna.tf32.f32 %0, %1;" : "=r"(r) : "f"(xf));
    return r;
}
__device__ __forceinline__ float tf32rna_f(float x) {
    uint32_t r;
    asm("cvt.rna.tf32.f32 %0, %1;" : "=r"(r) : "f"(x));
    return __uint_as_float(r);
}

__device__ __forceinline__ void mma_tf32(float c[4], uint32_t a0, uint32_t a1,
                                         uint32_t a2, uint32_t a3,
                                         uint32_t b0, uint32_t b1) {
    asm volatile(
        "mma.sync.aligned.m16n8k8.row.col.f32.tf32.tf32.f32 "
        "{%0,%1,%2,%3}, {%4,%5,%6,%7}, {%8,%9}, {%0,%1,%2,%3};"
        : "+f"(c[0]), "+f"(c[1]), "+f"(c[2]), "+f"(c[3])
        : "r"(a0), "r"(a1), "r"(a2), "r"(a3), "r"(b0), "r"(b1));
}

__device__ __forceinline__ float gelu_exact(float x) {
    return 0.5f * x * (1.0f + erff(x * 0.70710678118654752f));
}

#define GM_NONE 0
#define GM_GELU 1
#define GM_RES  2

// ============================================================================
// tf32 tensor-core GEMM: C[m,n] = sum_k A[m,k] * B[n,k]  (+ epilogue)
// CTA tile 128x128x16, 4 warps (2M x 2N), warp tile 64x64 (4x8 m16n8k8 tiles).
// Smem in fragment order: A-frag fetch = LDS.128, B-frag fetch = LDS.64.
// ============================================================================
template <int MODE>
__global__ __launch_bounds__(128, 2)
void gemm_tc(const float* __restrict__ A, const float* __restrict__ B,
             const float* __restrict__ Res, float* __restrict__ C,
             int M, int N, int K) {
    __shared__ __align__(16) char smA[2][8192];
    __shared__ __align__(16) char smB[2][8192];

    int tid = threadIdx.x;
    int wid = tid >> 5;
    int lane = tid & 31;
    int wm = wid >> 1;           // 0..1
    int wn = wid & 1;            // 0..1
    int g  = lane >> 2;          // 0..7
    int t4 = lane & 3;           // 0..3

    int m0 = blockIdx.y * 128;
    int n0 = blockIdx.x * 128;

    // staging coordinates: 4 float4 per matrix per thread
    int arow[4], ac4[4];
    uint32_t aob[4], bob[4];
#pragma unroll
    for (int q = 0; q < 4; q++) {
        int id = q * 128 + tid;
        int row = id >> 2;       // 0..127
        int c4  = id & 3;
        arow[q] = row; ac4[q] = c4;
        int s  = c4 >> 1;
        int kh = c4 & 1;
        int tm = row >> 4;
        int r  = kh * 2 + ((row & 15) >> 3);
        aob[q] = (uint32_t)(((tm * 2 + s) * 32 + (row & 7) * 4) * 16 + r * 4);
        int tn = row >> 3;
        bob[q] = (uint32_t)(((tn * 2 + s) * 32 + (row & 7) * 4) * 8 + kh * 4);
    }

    const float* Ag = A + (size_t)m0 * K;
    const float* Bg = B + (size_t)n0 * K;

    float acc[4][8][4];
#pragma unroll
    for (int i = 0; i < 4; i++)
#pragma unroll
        for (int j = 0; j < 8; j++)
#pragma unroll
            for (int r = 0; r < 4; r++) acc[i][j][r] = 0.f;

    int NT = K >> 4;

    uint4 ra[4], rb[4];
#pragma unroll
    for (int q = 0; q < 4; q++) {
        ra[q] = *reinterpret_cast<const uint4*>(Ag + (size_t)arow[q] * K + ac4[q] * 4);
        rb[q] = *reinterpret_cast<const uint4*>(Bg + (size_t)arow[q] * K + ac4[q] * 4);
    }
#pragma unroll
    for (int q = 0; q < 4; q++) {
        uint32_t av[4] = {ra[q].x, ra[q].y, ra[q].z, ra[q].w};
        uint32_t bv[4] = {rb[q].x, rb[q].y, rb[q].z, rb[q].w};
#pragma unroll
        for (int j = 0; j < 4; j++) {
            *reinterpret_cast<uint32_t*>(smA[0] + aob[q] + j * 16) = tf32rna_u(av[j]);
            *reinterpret_cast<uint32_t*>(smB[0] + bob[q] + j * 8)  = tf32rna_u(bv[j]);
        }
    }
    __syncthreads();

    for (int t = 0; t < NT; t++) {
        int buf = t & 1;
        if (t + 1 < NT) {
            int k0 = (t + 1) * 16;
#pragma unroll
            for (int q = 0; q < 4; q++) {
                ra[q] = *reinterpret_cast<const uint4*>(Ag + (size_t)arow[q] * K + k0 + ac4[q] * 4);
                rb[q] = *reinterpret_cast<const uint4*>(Bg + (size_t)arow[q] * K + k0 + ac4[q] * 4);
            }
        }

#pragma unroll
        for (int s = 0; s < 2; s++) {
            uint4 af[4];
            uint2 bf[8];
#pragma unroll
            for (int i = 0; i < 4; i++) {
                int tm = wm * 4 + i;
                af[i] = *reinterpret_cast<const uint4*>(
                    smA[buf] + ((tm * 2 + s) * 32 + lane) * 16);
            }
#pragma unroll
            for (int j = 0; j < 8; j++) {
                int tn = wn * 8 + j;
                bf[j] = *reinterpret_cast<const uint2*>(
                    smB[buf] + ((tn * 2 + s) * 32 + lane) * 8);
            }
#pragma unroll
            for (int i = 0; i < 4; i++)
#pragma unroll
                for (int j = 0; j < 8; j++)
                    mma_tf32(acc[i][j], af[i].x, af[i].y, af[i].z, af[i].w,
                             bf[j].x, bf[j].y);
        }

        if (t + 1 < NT) {
#pragma unroll
            for (int q = 0; q < 4; q++) {
                uint32_t av[4] = {ra[q].x, ra[q].y, ra[q].z, ra[q].w};
                uint32_t bv[4] = {rb[q].x, rb[q].y, rb[q].z, rb[q].w};
#pragma unroll
                for (int j = 0; j < 4; j++) {
                    *reinterpret_cast<uint32_t*>(smA[buf ^ 1] + aob[q] + j * 16) = tf32rna_u(av[j]);
                    *reinterpret_cast<uint32_t*>(smB[buf ^ 1] + bob[q] + j * 8)  = tf32rna_u(bv[j]);
                }
            }
        }
        __syncthreads();
    }

    // epilogue
#pragma unroll
    for (int i = 0; i < 4; i++) {
#pragma unroll
        for (int j = 0; j < 8; j++) {
            int mlo = m0 + wm * 64 + i * 16 + g;
            int n   = n0 + wn * 64 + j * 8 + t4 * 2;
            float2 v0 = make_float2(acc[i][j][0], acc[i][j][1]);
            float2 v1 = make_float2(acc[i][j][2], acc[i][j][3]);
            if (MODE == GM_GELU) {
                v0.x = gelu_exact(v0.x); v0.y = gelu_exact(v0.y);
                v1.x = gelu_exact(v1.x); v1.y = gelu_exact(v1.y);
            }
            if (MODE == GM_RES) {
                float2 r0 = *reinterpret_cast<const float2*>(Res + (size_t)mlo * N + n);
                float2 r1 = *reinterpret_cast<const float2*>(Res + (size_t)(mlo + 8) * N + n);
                v0.x += r0.x; v0.y += r0.y;
                v1.x += r1.x; v1.y += r1.y;
            }
            *reinterpret_cast<float2*>(C + (size_t)mlo * N + n) = v0;
            *reinterpret_cast<float2*>(C + (size_t)(mlo + 8) * N + n) = v1;
        }
    }
}

// ---------------- rmsnorm ----------------
__global__ void rmsnorm_kernel(const float* __restrict__ x,
                               const float* __restrict__ w,
                               float* __restrict__ out) {
    int row = blockIdx.x;
    int tid = threadIdx.x;
    const float4* x4 = reinterpret_cast<const float4*>(x + (size_t)row * DM);
    const float4* w4 = reinterpret_cast<const float4*>(w);
    float4* o4 = reinterpret_cast<float4*>(out + (size_t)row * DM);
    float4 v = x4[tid];
    float ss = v.x * v.x + v.y * v.y + v.z * v.z + v.w * v.w;
#pragma unroll
    for (int off = 16; off; off >>= 1)
        ss += __shfl_xor_sync(0xffffffffu, ss, off);
    __shared__ float sred[8];
    __shared__ float stot;
    if ((tid & 31) == 0) sred[tid >> 5] = ss;
    __syncthreads();
    if (tid == 0) {
        float t = 0.f;
#pragma unroll
        for (int i = 0; i < 8; i++) t += sred[i];
        stot = rsqrtf(t * (1.0f / DM) + 1e-5f);
    }
    __syncthreads();
    float rinv = stot;
    float4 wv = w4[tid];
    float4 r;
    r.x = wv.x * v.x * rinv;
    r.y = wv.y * v.y * rinv;
    r.z = wv.z * v.z * rinv;
    r.w = wv.w * v.w * rinv;
    o4[tid] = r;
}

// ============================================================================
// Tensor-core causal flash attention (tf32).
// Bq=128 (8 warps x 16 rows), Bk=64, dk=64. Grid (16, 16, 2), 256 threads.
// Dyn smem: Qs[128][68] + Ks[64][68] + Vs[64][72] + Pw[8][16][68]
// ============================================================================
#define QS_PAD 68
#define KS_PAD 68
#define VS_PAD 72
#define PW_PAD 68
#define ATT_SMEM_FLOATS (128 * QS_PAD + 64 * KS_PAD + 64 * VS_PAD + 8 * 16 * PW_PAD)
#define ATT_SMEM_BYTES  (ATT_SMEM_FLOATS * 4)

__global__ __launch_bounds__(256, 2)
void attn_tc(const float* __restrict__ q, const float* __restrict__ k,
             const float* __restrict__ v, float* __restrict__ o) {
    extern __shared__ float sm[];
    float* Qs = sm;                              // 128*68
    float* Ks = Qs + 128 * QS_PAD;               // 64*68
    float* Vs = Ks + 64 * KS_PAD;                // 64*72
    float* Pw = Vs + 64 * VS_PAD;                // 8*16*68

    int qb  = blockIdx.x;        // 0..15
    int h   = blockIdx.y;
    int b   = blockIdx.z;
    int tid = threadIdx.x;
    int wid = tid >> 5;
    int lane = tid & 31;
    int g  = lane >> 2;
    int t4 = lane & 3;
    int row0 = b * 2048;
    int col0 = h * 64;

    int qrowg = qb * 128 + wid * 16;             // warp strip start (seq index)
    float* Pme = Pw + wid * 16 * PW_PAD;

    // stage Q block (128x64), scaled by 0.125, tf32-rounded
#pragma unroll
    for (int it = 0; it < 8; it++) {
        int id = it * 256 + tid;
        int r  = id >> 4;            // 0..127
        int c4 = id & 15;
        float4 val = *reinterpret_cast<const float4*>(
            q + (size_t)(row0 + qb * 128 + r) * DM + col0 + c4 * 4);
        val.x = tf32rna_f(val.x * 0.125f);
        val.y = tf32rna_f(val.y * 0.125f);
        val.z = tf32rna_f(val.z * 0.125f);
        val.w = tf32rna_f(val.w * 0.125f);
        *reinterpret_cast<float4*>(&Qs[r * QS_PAD + c4 * 4]) = val;
    }

    float m_i[2] = {-1e30f, -1e30f};
    float l_i[2] = {0.f, 0.f};
    float oacc[8][4];
#pragma unroll
    for (int j = 0; j < 8; j++)
#pragma unroll
        for (int r = 0; r < 4; r++) oacc[j][r] = 0.f;

    int nkb = 2 * qb + 2;
    for (int jb = 0; jb < nkb; jb++) {
        __syncthreads();
        // stage K, V (64x64 each), tf32-rounded
#pragma unroll
        for (int it = 0; it < 4; it++) {
            int id = it * 256 + tid;
            int r  = id >> 4;        // 0..63
            int c4 = id & 15;
            size_t gi = (size_t)(row0 + jb * 64 + r) * DM + col0 + c4 * 4;
            float4 kv = *reinterpret_cast<const float4*>(k + gi);
            kv.x = tf32rna_f(kv.x); kv.y = tf32rna_f(kv.y);
            kv.z = tf32rna_f(kv.z); kv.w = tf32rna_f(kv.w);
            *reinterpret_cast<float4*>(&Ks[r * KS_PAD + c4 * 4]) = kv;
            float4 vv = *reinterpret_cast<const float4*>(v + gi);
            vv.x = tf32rna_f(vv.x); vv.y = tf32rna_f(vv.y);
            vv.z = tf32rna_f(vv.z); vv.w = tf32rna_f(vv.w);
            *reinterpret_cast<float4*>(&Vs[r * VS_PAD + c4 * 4]) = vv;
        }
        __syncthreads();

        // fully masked for this warp's strip? (keys all > last row)
        if (jb * 64 > qrowg + 15) continue;
        bool full_vis = (jb * 64 + 63 <= qrowg);

        // ---- S = Q K^T (warp strip 16 x 64) ----
        float sacc[8][4];
#pragma unroll
        for (int j = 0; j < 8; j++)
#pragma unroll
            for (int r = 0; r < 4; r++) sacc[j][r] = 0.f;

#pragma unroll
        for (int s = 0; s < 8; s++) {
            int qr = wid * 16;
            uint32_t a0 = __float_as_uint(Qs[(qr + g) * QS_PAD + s * 8 + t4]);
            uint32_t a1 = __float_as_uint(Qs[(qr + g + 8) * QS_PAD + s * 8 + t4]);
            uint32_t a2 = __float_as_uint(Qs[(qr + g) * QS_PAD + s * 8 + t4 + 4]);
            uint32_t a3 = __float_as_uint(Qs[(qr + g + 8) * QS_PAD + s * 8 + t4 + 4]);
#pragma unroll
            for (int jn = 0; jn < 8; jn++) {
                uint32_t b0 = __float_as_uint(Ks[(jn * 8 + g) * KS_PAD + s * 8 + t4]);
                uint32_t b1 = __float_as_uint(Ks[(jn * 8 + g) * KS_PAD + s * 8 + t4 + 4]);
                mma_tf32(sacc[jn], a0, a1, a2, a3, b0, b1);
            }
        }

        // ---- causal mask ----
        if (!full_vis) {
            int colb = jb * 64 + 2 * t4;
            int r0i = qrowg + g;
            int r1i = qrowg + g + 8;
#pragma unroll
            for (int jn = 0; jn < 8; jn++) {
                int c = colb + jn * 8;
                if (c     > r0i) sacc[jn][0] = -1e30f;
                if (c + 1 > r0i) sacc[jn][1] = -1e30f;
                if (c     > r1i) sacc[jn][2] = -1e30f;
                if (c + 1 > r1i) sacc[jn][3] = -1e30f;
            }
        }

        // ---- online softmax (2 rows per lane: g and g+8) ----
#pragma unroll
        for (int half = 0; half < 2; half++) {
            int e0 = half * 2;
            float mx = -1e30f;
#pragma unroll
            for (int jn = 0; jn < 8; jn++)
                mx = fmaxf(mx, fmaxf(sacc[jn][e0], sacc[jn][e0 + 1]));
            mx = fmaxf(mx, __shfl_xor_sync(0xffffffffu, mx, 1));
            mx = fmaxf(mx, __shfl_xor_sync(0xffffffffu, mx, 2));
            float mnew = fmaxf(m_i[half], mx);
            float alpha = __expf(m_i[half] - mnew);
            float rs = 0.f;
            int prow = (g + 8 * half) * PW_PAD + 2 * t4;
#pragma unroll
            for (int jn = 0; jn < 8; jn++) {
                float p0 = __expf(sacc[jn][e0] - mnew);
                float p1 = __expf(sacc[jn][e0 + 1] - mnew);
                rs += p0 + p1;
                float2 pv = make_float2(tf32rna_f(p0), tf32rna_f(p1));
                *reinterpret_cast<float2*>(&Pme[prow + jn * 8]) = pv;
            }
            rs += __shfl_xor_sync(0xffffffffu, rs, 1);
            rs += __shfl_xor_sync(0xffffffffu, rs, 2);
            l_i[half] = l_i[half] * alpha + rs;
            m_i[half] = mnew;
#pragma unroll
            for (int jn = 0; jn < 8; jn++) {
                oacc[jn][e0]     *= alpha;
                oacc[jn][e0 + 1] *= alpha;
            }
        }
        __syncwarp();

        // ---- O += P V ----
#pragma unroll
        for (int s = 0; s < 8; s++) {
            uint32_t a0 = __float_as_uint(Pme[g * PW_PAD + s * 8 + t4]);
            uint32_t a1 = __float_as_uint(Pme[(g + 8) * PW_PAD + s * 8 + t4]);
            uint32_t a2 = __float_as_uint(Pme[g * PW_PAD + s * 8 + t4 + 4]);
            uint32_t a3 = __float_as_uint(Pme[(g + 8) * PW_PAD + s * 8 + t4 + 4]);
#pragma unroll
            for (int jn = 0; jn < 8; jn++) {
                uint32_t b0 = __float_as_uint(Vs[(s * 8 + t4) * VS_PAD + jn * 8 + g]);
                uint32_t b1 = __float_as_uint(Vs[(s * 8 + t4 + 4) * VS_PAD + jn * 8 + g]);
                mma_tf32(oacc[jn], a0, a1, a2, a3, b0, b1);
            }
        }
        __syncwarp();
    }

    // ---- write output ----
#pragma unroll
    for (int half = 0; half < 2; half++) {
        float inv = 1.0f / l_i[half];
        int r = row0 + qrowg + g + 8 * half;
        int e0 = half * 2;
#pragma unroll
        for (int jn = 0; jn < 8; jn++) {
            float2 ov = make_float2(oacc[jn][e0] * inv, oacc[jn][e0 + 1] * inv);
            *reinterpret_cast<float2*>(o + (size_t)r * DM + col0 + jn * 8 + 2 * t4) = ov;
        }
    }
}

// ---------------- launch ----------------
extern "C" void kernel_launch(void* const* d_in, const int* in_sizes, int n_in,
                              void* d_out, int out_size) {
    const float* x     = (const float*)d_in[0];
    const float* wq    = (const float*)d_in[1];
    const float* wk    = (const float*)d_in[2];
    const float* wv    = (const float*)d_in[3];
    const float* wo    = (const float*)d_in[4];
    const float* ln1_w = (const float*)d_in[5];
    const float* ln2_w = (const float*)d_in[6];
    const float* w1    = (const float*)d_in[7];
    const float* w2    = (const float*)d_in[8];
    float* out = (float*)d_out;

    float *p_xn, *p_q, *p_k, *p_v, *p_attn, *p_x1, *p_h;
    cudaGetSymbolAddress((void**)&p_xn, g_xn);
    cudaGetSymbolAddress((void**)&p_q, g_q);
    cudaGetSymbolAddress((void**)&p_k, g_k);
    cudaGetSymbolAddress((void**)&p_v, g_v);
    cudaGetSymbolAddress((void**)&p_attn, g_attn);
    cudaGetSymbolAddress((void**)&p_x1, g_x1);
    cudaGetSymbolAddress((void**)&p_h, g_h);

    cudaFuncSetAttribute(attn_tc, cudaFuncAttributeMaxDynamicSharedMemorySize,
                         ATT_SMEM_BYTES);

    dim3 gd_1024(DM / 128, MT / 128);   // 8 x 32
    dim3 gd_ff(DFF / 128, MT / 128);    // 32 x 32

    // 1. xn1 = rmsnorm(x, ln1_w)
    rmsnorm_kernel<<<MT, 256>>>(x, ln1_w, p_xn);

    // 2. Q, K, V
    gemm_tc<GM_NONE><<<gd_1024, 128>>>(p_xn, wq, nullptr, p_q, MT, DM, DM);
    gemm_tc<GM_NONE><<<gd_1024, 128>>>(p_xn, wk, nullptr, p_k, MT, DM, DM);
    gemm_tc<GM_NONE><<<gd_1024, 128>>>(p_xn, wv, nullptr, p_v, MT, DM, DM);

    // 3. causal flash attention (tensor cores)
    attn_tc<<<dim3(16, 16, 2), 256, ATT_SMEM_BYTES>>>(p_q, p_k, p_v, p_attn);

    // 4. x1 = x + attn @ wo.T
    gemm_tc<GM_RES><<<gd_1024, 128>>>(p_attn, wo, x, p_x1, MT, DM, DM);

    // 5. xn2 = rmsnorm(x1, ln2_w)
    rmsnorm_kernel<<<MT, 256>>>(p_x1, ln2_w, p_xn);

    // 6. h = gelu(xn2 @ w1.T)
    gemm_tc<GM_GELU><<<gd_ff, 128>>>(p_xn, w1, nullptr, p_h, MT, DFF, DM);

    // 7. out = x1 + h @ w2.T
    gemm_tc<GM_RES><<<gd_1024, 128>>>(p_h, w2, p_x1, out, MT, DM, DFF);
}

// round 5
// speedup vs baseline: 4.2227x; 1.5641x over previous
#include <cuda_runtime.h>
#include <math.h>
#include <stdint.h>

#define MT   4096    // B*T rows
#define DM   1024
#define DFF  4096

// ---------------- scratch (device globals; no allocation allowed) -----------
__device__ float g_xn[MT * DM];
__device__ float g_q[MT * DM];
__device__ float g_k[MT * DM];
__device__ float g_v[MT * DM];
__device__ float g_attn[MT * DM];
__device__ float g_x1[MT * DM];
__device__ float g_h[MT * DFF];
// tf32-rounded weights
__device__ float g_wq[DM * DM];
__device__ float g_wk[DM * DM];
__device__ float g_wv[DM * DM];
__device__ float g_wo[DM * DM];
__device__ float g_w1[DFF * DM];
__device__ float g_w2[DM * DFF];

// ---------------- helpers ----------------
__device__ __forceinline__ float tf32rna_f(float x) {
    uint32_t r;
    asm("cvt.rna.tf32.f32 %0, %1;" : "=r"(r) : "f"(x));
    return __uint_as_float(r);
}

__device__ __forceinline__ void mma_tf32(float c[4], uint32_t a0, uint32_t a1,
                                         uint32_t a2, uint32_t a3,
                                         uint32_t b0, uint32_t b1) {
    asm volatile(
        "mma.sync.aligned.m16n8k8.row.col.f32.tf32.tf32.f32 "
        "{%0,%1,%2,%3}, {%4,%5,%6,%7}, {%8,%9}, {%0,%1,%2,%3};"
        : "+f"(c[0]), "+f"(c[1]), "+f"(c[2]), "+f"(c[3])
        : "r"(a0), "r"(a1), "r"(a2), "r"(a3), "r"(b0), "r"(b1));
}

__device__ __forceinline__ float gelu_exact(float x) {
    return 0.5f * x * (1.0f + erff(x * 0.70710678118654752f));
}

__device__ __forceinline__ void cp_async16(uint32_t smaddr, const void* gptr) {
    asm volatile("cp.async.cg.shared.global [%0], [%1], 16;"
                 :: "r"(smaddr), "l"(gptr) : "memory");
}
#define CP_COMMIT()  asm volatile("cp.async.commit_group;" ::: "memory")
#define CP_WAIT(n)   asm volatile("cp.async.wait_group %0;" :: "n"(n) : "memory")

#define GM_NONE 0
#define GM_GELU 1
#define GM_RES  2

// ---------------- weight tf32 pre-round ----------------
__global__ void roundw_kernel(const float* __restrict__ src,
                              float* __restrict__ dst, int n4) {
    int i = blockIdx.x * blockDim.x + threadIdx.x;
    if (i < n4) {
        float4 v = reinterpret_cast<const float4*>(src)[i];
        v.x = tf32rna_f(v.x); v.y = tf32rna_f(v.y);
        v.z = tf32rna_f(v.z); v.w = tf32rna_f(v.w);
        reinterpret_cast<float4*>(dst)[i] = v;
    }
}

// ============================================================================
// tf32 tensor-core GEMM: C[m,n] = sum_k A[m,k] * B[n,k]  (+ epilogue)
// Inputs MUST be pre-rounded to tf32 values (still fp32 storage).
// CTA tile 128x128x32, 4 warps (2M x 2N), warp tile 64x64.
// 3-stage cp.async pipeline; smem rows 128B with chunk swizzle c^=(row&7).
// ============================================================================
#define KT 32
#define TILEB (128 * KT * 4)             // 16 KB
#define GEMM_SMEM (3 * 2 * TILEB)        // 96 KB

template <int MODE>
__global__ __launch_bounds__(128, 2)
void gemm_tc(const float* __restrict__ A, const float* __restrict__ B,
             const float* __restrict__ Res, float* __restrict__ C,
             int M, int N, int K) {
    extern __shared__ char sm[];
    uint32_t smb = (uint32_t)__cvta_generic_to_shared(sm);

    int tid = threadIdx.x;
    int wid = tid >> 5;
    int lane = tid & 31;
    int wm = wid >> 1;
    int wn = wid & 1;
    int g  = lane >> 2;
    int t4 = lane & 3;

    int m0 = blockIdx.y * 128;
    int n0 = blockIdx.x * 128;
    const float* Ag = A + (size_t)m0 * K;
    const float* Bg = B + (size_t)n0 * K;

    // cp.async coordinates: 8 chunks per matrix per thread
    int crow[8]; uint32_t coff[8];
#pragma unroll
    for (int it = 0; it < 8; it++) {
        int idx = it * 128 + tid;
        int r = idx >> 3;
        int c = idx & 7;
        crow[it] = r;
        coff[it] = (uint32_t)(r * 128 + ((c ^ (r & 7)) << 4));
    }
    int cchunk[8];
#pragma unroll
    for (int it = 0; it < 8; it++) cchunk[it] = (it * 128 + tid) & 7;

    float acc[4][8][4];
#pragma unroll
    for (int i = 0; i < 4; i++)
#pragma unroll
        for (int j = 0; j < 8; j++)
#pragma unroll
            for (int r = 0; r < 4; r++) acc[i][j][r] = 0.f;

    int NT = K / KT;

    // issue stage
    auto issue = [&](int t, int st) {
        uint32_t As = smb + st * 2 * TILEB;
        uint32_t Bs = As + TILEB;
        const float* Agt = Ag + t * KT;
        const float* Bgt = Bg + t * KT;
#pragma unroll
        for (int it = 0; it < 8; it++) {
            const float* ga = Agt + (size_t)crow[it] * K + cchunk[it] * 4;
            const float* gb = Bgt + (size_t)crow[it] * K + cchunk[it] * 4;
            cp_async16(As + coff[it], ga);
            cp_async16(Bs + coff[it], gb);
        }
    };

    issue(0, 0); CP_COMMIT();
    if (NT > 1) issue(1, 1);
    CP_COMMIT();

    for (int t = 0; t < NT; t++) {
        int st = t % 3;
        CP_WAIT(1);
        __syncthreads();

        uint32_t As = smb + st * 2 * TILEB;
        uint32_t Bs = As + TILEB;
        // warp base rows (bytes): A rows wm*64.., B rows wn*64..
#pragma unroll
        for (int s = 0; s < 4; s++) {
            uint32_t af[4][4];
#pragma unroll
            for (int i = 0; i < 4; i++) {
                uint32_t row = (uint32_t)(wm * 64 + i * 16 + g);
                uint32_t base = As + row * 128 + (t4 << 2);
                uint32_t c0 = (uint32_t)(((2 * s) ^ g) << 4);
                uint32_t c1 = (uint32_t)(((2 * s + 1) ^ g) << 4);
                asm volatile("ld.shared.b32 %0, [%1];" : "=r"(af[i][0]) : "r"(base + c0));
                asm volatile("ld.shared.b32 %0, [%1];" : "=r"(af[i][1]) : "r"(base + c0 + 1024));
                asm volatile("ld.shared.b32 %0, [%1];" : "=r"(af[i][2]) : "r"(base + c1));
                asm volatile("ld.shared.b32 %0, [%1];" : "=r"(af[i][3]) : "r"(base + c1 + 1024));
            }
            uint32_t bf[8][2];
#pragma unroll
            for (int j = 0; j < 8; j++) {
                uint32_t row = (uint32_t)(wn * 64 + j * 8 + g);
                uint32_t base = Bs + row * 128 + (t4 << 2);
                uint32_t c0 = (uint32_t)(((2 * s) ^ g) << 4);
                uint32_t c1 = (uint32_t)(((2 * s + 1) ^ g) << 4);
                asm volatile("ld.shared.b32 %0, [%1];" : "=r"(bf[j][0]) : "r"(base + c0));
                asm volatile("ld.shared.b32 %0, [%1];" : "=r"(bf[j][1]) : "r"(base + c1));
            }
#pragma unroll
            for (int i = 0; i < 4; i++)
#pragma unroll
                for (int j = 0; j < 8; j++)
                    mma_tf32(acc[i][j], af[i][0], af[i][1], af[i][2], af[i][3],
                             bf[j][0], bf[j][1]);
        }

        if (t + 2 < NT) issue(t + 2, (t + 2) % 3);
        CP_COMMIT();
    }

    // epilogue
#pragma unroll
    for (int i = 0; i < 4; i++) {
#pragma unroll
        for (int j = 0; j < 8; j++) {
            int mlo = m0 + wm * 64 + i * 16 + g;
            int n   = n0 + wn * 64 + j * 8 + t4 * 2;
            float2 v0 = make_float2(acc[i][j][0], acc[i][j][1]);
            float2 v1 = make_float2(acc[i][j][2], acc[i][j][3]);
            if (MODE == GM_GELU) {
                v0.x = tf32rna_f(gelu_exact(v0.x));
                v0.y = tf32rna_f(gelu_exact(v0.y));
                v1.x = tf32rna_f(gelu_exact(v1.x));
                v1.y = tf32rna_f(gelu_exact(v1.y));
            }
            if (MODE == GM_RES) {
                float2 r0 = *reinterpret_cast<const float2*>(Res + (size_t)mlo * N + n);
                float2 r1 = *reinterpret_cast<const float2*>(Res + (size_t)(mlo + 8) * N + n);
                v0.x += r0.x; v0.y += r0.y;
                v1.x += r1.x; v1.y += r1.y;
            }
            *reinterpret_cast<float2*>(C + (size_t)mlo * N + n) = v0;
            *reinterpret_cast<float2*>(C + (size_t)(mlo + 8) * N + n) = v1;
        }
    }
}

// ---------------- rmsnorm (emits tf32-rounded output; feeds GEMMs only) -----
__global__ void rmsnorm_kernel(const float* __restrict__ x,
                               const float* __restrict__ w,
                               float* __restrict__ out) {
    int row = blockIdx.x;
    int tid = threadIdx.x;
    const float4* x4 = reinterpret_cast<const float4*>(x + (size_t)row * DM);
    const float4* w4 = reinterpret_cast<const float4*>(w);
    float4* o4 = reinterpret_cast<float4*>(out + (size_t)row * DM);
    float4 v = x4[tid];
    float ss = v.x * v.x + v.y * v.y + v.z * v.z + v.w * v.w;
#pragma unroll
    for (int off = 16; off; off >>= 1)
        ss += __shfl_xor_sync(0xffffffffu, ss, off);
    __shared__ float sred[8];
    __shared__ float stot;
    if ((tid & 31) == 0) sred[tid >> 5] = ss;
    __syncthreads();
    if (tid == 0) {
        float t = 0.f;
#pragma unroll
        for (int i = 0; i < 8; i++) t += sred[i];
        stot = rsqrtf(t * (1.0f / DM) + 1e-5f);
    }
    __syncthreads();
    float rinv = stot;
    float4 wv = w4[tid];
    float4 r;
    r.x = tf32rna_f(wv.x * v.x * rinv);
    r.y = tf32rna_f(wv.y * v.y * rinv);
    r.z = tf32rna_f(wv.z * v.z * rinv);
    r.w = tf32rna_f(wv.w * v.w * rinv);
    o4[tid] = r;
}

// ============================================================================
// Tensor-core causal flash attention (tf32) — unchanged from R4 except the
// output write is tf32-rounded (it feeds only the wo GEMM).
// ============================================================================
#define QS_PAD 68
#define KS_PAD 68
#define VS_PAD 72
#define PW_PAD 68
#define ATT_SMEM_FLOATS (128 * QS_PAD + 64 * KS_PAD + 64 * VS_PAD + 8 * 16 * PW_PAD)
#define ATT_SMEM_BYTES  (ATT_SMEM_FLOATS * 4)

__global__ __launch_bounds__(256, 2)
void attn_tc(const float* __restrict__ q, const float* __restrict__ k,
             const float* __restrict__ v, float* __restrict__ o) {
    extern __shared__ float smf[];
    float* Qs = smf;
    float* Ks = Qs + 128 * QS_PAD;
    float* Vs = Ks + 64 * KS_PAD;
    float* Pw = Vs + 64 * VS_PAD;

    int qb  = blockIdx.x;
    int h   = blockIdx.y;
    int b   = blockIdx.z;
    int tid = threadIdx.x;
    int wid = tid >> 5;
    int lane = tid & 31;
    int g  = lane >> 2;
    int t4 = lane & 3;
    int row0 = b * 2048;
    int col0 = h * 64;

    int qrowg = qb * 128 + wid * 16;
    float* Pme = Pw + wid * 16 * PW_PAD;

#pragma unroll
    for (int it = 0; it < 8; it++) {
        int id = it * 256 + tid;
        int r  = id >> 4;
        int c4 = id & 15;
        float4 val = *reinterpret_cast<const float4*>(
            q + (size_t)(row0 + qb * 128 + r) * DM + col0 + c4 * 4);
        val.x = tf32rna_f(val.x * 0.125f);
        val.y = tf32rna_f(val.y * 0.125f);
        val.z = tf32rna_f(val.z * 0.125f);
        val.w = tf32rna_f(val.w * 0.125f);
        *reinterpret_cast<float4*>(&Qs[r * QS_PAD + c4 * 4]) = val;
    }

    float m_i[2] = {-1e30f, -1e30f};
    float l_i[2] = {0.f, 0.f};
    float oacc[8][4];
#pragma unroll
    for (int j = 0; j < 8; j++)
#pragma unroll
        for (int r = 0; r < 4; r++) oacc[j][r] = 0.f;

    int nkb = 2 * qb + 2;
    for (int jb = 0; jb < nkb; jb++) {
        __syncthreads();
#pragma unroll
        for (int it = 0; it < 4; it++) {
            int id = it * 256 + tid;
            int r  = id >> 4;
            int c4 = id & 15;
            size_t gi = (size_t)(row0 + jb * 64 + r) * DM + col0 + c4 * 4;
            float4 kv = *reinterpret_cast<const float4*>(k + gi);
            kv.x = tf32rna_f(kv.x); kv.y = tf32rna_f(kv.y);
            kv.z = tf32rna_f(kv.z); kv.w = tf32rna_f(kv.w);
            *reinterpret_cast<float4*>(&Ks[r * KS_PAD + c4 * 4]) = kv;
            float4 vv = *reinterpret_cast<const float4*>(v + gi);
            vv.x = tf32rna_f(vv.x); vv.y = tf32rna_f(vv.y);
            vv.z = tf32rna_f(vv.z); vv.w = tf32rna_f(vv.w);
            *reinterpret_cast<float4*>(&Vs[r * VS_PAD + c4 * 4]) = vv;
        }
        __syncthreads();

        if (jb * 64 > qrowg + 15) continue;
        bool full_vis = (jb * 64 + 63 <= qrowg);

        float sacc[8][4];
#pragma unroll
        for (int j = 0; j < 8; j++)
#pragma unroll
            for (int r = 0; r < 4; r++) sacc[j][r] = 0.f;

#pragma unroll
        for (int s = 0; s < 8; s++) {
            int qr = wid * 16;
            uint32_t a0 = __float_as_uint(Qs[(qr + g) * QS_PAD + s * 8 + t4]);
            uint32_t a1 = __float_as_uint(Qs[(qr + g + 8) * QS_PAD + s * 8 + t4]);
            uint32_t a2 = __float_as_uint(Qs[(qr + g) * QS_PAD + s * 8 + t4 + 4]);
            uint32_t a3 = __float_as_uint(Qs[(qr + g + 8) * QS_PAD + s * 8 + t4 + 4]);
#pragma unroll
            for (int jn = 0; jn < 8; jn++) {
                uint32_t b0 = __float_as_uint(Ks[(jn * 8 + g) * KS_PAD + s * 8 + t4]);
                uint32_t b1 = __float_as_uint(Ks[(jn * 8 + g) * KS_PAD + s * 8 + t4 + 4]);
                mma_tf32(sacc[jn], a0, a1, a2, a3, b0, b1);
            }
        }

        if (!full_vis) {
            int colb = jb * 64 + 2 * t4;
            int r0i = qrowg + g;
            int r1i = qrowg + g + 8;
#pragma unroll
            for (int jn = 0; jn < 8; jn++) {
                int c = colb + jn * 8;
                if (c     > r0i) sacc[jn][0] = -1e30f;
                if (c + 1 > r0i) sacc[jn][1] = -1e30f;
                if (c     > r1i) sacc[jn][2] = -1e30f;
                if (c + 1 > r1i) sacc[jn][3] = -1e30f;
            }
        }

#pragma unroll
        for (int half = 0; half < 2; half++) {
            int e0 = half * 2;
            float mx = -1e30f;
#pragma unroll
            for (int jn = 0; jn < 8; jn++)
                mx = fmaxf(mx, fmaxf(sacc[jn][e0], sacc[jn][e0 + 1]));
            mx = fmaxf(mx, __shfl_xor_sync(0xffffffffu, mx, 1));
            mx = fmaxf(mx, __shfl_xor_sync(0xffffffffu, mx, 2));
            float mnew = fmaxf(m_i[half], mx);
            float alpha = __expf(m_i[half] - mnew);
            float rs = 0.f;
            int prow = (g + 8 * half) * PW_PAD + 2 * t4;
#pragma unroll
            for (int jn = 0; jn < 8; jn++) {
                float p0 = __expf(sacc[jn][e0] - mnew);
                float p1 = __expf(sacc[jn][e0 + 1] - mnew);
                rs += p0 + p1;
                float2 pv = make_float2(tf32rna_f(p0), tf32rna_f(p1));
                *reinterpret_cast<float2*>(&Pme[prow + jn * 8]) = pv;
            }
            rs += __shfl_xor_sync(0xffffffffu, rs, 1);
            rs += __shfl_xor_sync(0xffffffffu, rs, 2);
            l_i[half] = l_i[half] * alpha + rs;
            m_i[half] = mnew;
#pragma unroll
            for (int jn = 0; jn < 8; jn++) {
                oacc[jn][e0]     *= alpha;
                oacc[jn][e0 + 1] *= alpha;
            }
        }
        __syncwarp();

#pragma unroll
        for (int s = 0; s < 8; s++) {
            uint32_t a0 = __float_as_uint(Pme[g * PW_PAD + s * 8 + t4]);
            uint32_t a1 = __float_as_uint(Pme[(g + 8) * PW_PAD + s * 8 + t4]);
            uint32_t a2 = __float_as_uint(Pme[g * PW_PAD + s * 8 + t4 + 4]);
            uint32_t a3 = __float_as_uint(Pme[(g + 8) * PW_PAD + s * 8 + t4 + 4]);
#pragma unroll
            for (int jn = 0; jn < 8; jn++) {
                uint32_t b0 = __float_as_uint(Vs[(s * 8 + t4) * VS_PAD + jn * 8 + g]);
                uint32_t b1 = __float_as_uint(Vs[(s * 8 + t4 + 4) * VS_PAD + jn * 8 + g]);
                mma_tf32(oacc[jn], a0, a1, a2, a3, b0, b1);
            }
        }
        __syncwarp();
    }

#pragma unroll
    for (int half = 0; half < 2; half++) {
        float inv = 1.0f / l_i[half];
        int r = row0 + qrowg + g + 8 * half;
        int e0 = half * 2;
#pragma unroll
        for (int jn = 0; jn < 8; jn++) {
            float2 ov = make_float2(tf32rna_f(oacc[jn][e0] * inv),
                                    tf32rna_f(oacc[jn][e0 + 1] * inv));
            *reinterpret_cast<float2*>(o + (size_t)r * DM + col0 + jn * 8 + 2 * t4) = ov;
        }
    }
}

// ---------------- launch ----------------
extern "C" void kernel_launch(void* const* d_in, const int* in_sizes, int n_in,
                              void* d_out, int out_size) {
    const float* x     = (const float*)d_in[0];
    const float* wq    = (const float*)d_in[1];
    const float* wk    = (const float*)d_in[2];
    const float* wv    = (const float*)d_in[3];
    const float* wo    = (const float*)d_in[4];
    const float* ln1_w = (const float*)d_in[5];
    const float* ln2_w = (const float*)d_in[6];
    const float* w1    = (const float*)d_in[7];
    const float* w2    = (const float*)d_in[8];
    float* out = (float*)d_out;

    float *p_xn, *p_q, *p_k, *p_v, *p_attn, *p_x1, *p_h;
    float *p_wq, *p_wk, *p_wv, *p_wo, *p_w1, *p_w2;
    cudaGetSymbolAddress((void**)&p_xn, g_xn);
    cudaGetSymbolAddress((void**)&p_q, g_q);
    cudaGetSymbolAddress((void**)&p_k, g_k);
    cudaGetSymbolAddress((void**)&p_v, g_v);
    cudaGetSymbolAddress((void**)&p_attn, g_attn);
    cudaGetSymbolAddress((void**)&p_x1, g_x1);
    cudaGetSymbolAddress((void**)&p_h, g_h);
    cudaGetSymbolAddress((void**)&p_wq, g_wq);
    cudaGetSymbolAddress((void**)&p_wk, g_wk);
    cudaGetSymbolAddress((void**)&p_wv, g_wv);
    cudaGetSymbolAddress((void**)&p_wo, g_wo);
    cudaGetSymbolAddress((void**)&p_w1, g_w1);
    cudaGetSymbolAddress((void**)&p_w2, g_w2);

    cudaFuncSetAttribute(gemm_tc<GM_NONE>, cudaFuncAttributeMaxDynamicSharedMemorySize, GEMM_SMEM);
    cudaFuncSetAttribute(gemm_tc<GM_GELU>, cudaFuncAttributeMaxDynamicSharedMemorySize, GEMM_SMEM);
    cudaFuncSetAttribute(gemm_tc<GM_RES>,  cudaFuncAttributeMaxDynamicSharedMemorySize, GEMM_SMEM);
    cudaFuncSetAttribute(attn_tc, cudaFuncAttributeMaxDynamicSharedMemorySize, ATT_SMEM_BYTES);

    dim3 gd_1024(DM / 128, MT / 128);
    dim3 gd_ff(DFF / 128, MT / 128);

    // 0. pre-round weights to tf32 values
    int n4a = DM * DM / 4;
    int n4f = DFF * DM / 4;
    roundw_kernel<<<(n4a + 255) / 256, 256>>>(wq, p_wq, n4a);
    roundw_kernel<<<(n4a + 255) / 256, 256>>>(wk, p_wk, n4a);
    roundw_kernel<<<(n4a + 255) / 256, 256>>>(wv, p_wv, n4a);
    roundw_kernel<<<(n4a + 255) / 256, 256>>>(wo, p_wo, n4a);
    roundw_kernel<<<(n4f + 255) / 256, 256>>>(w1, p_w1, n4f);
    roundw_kernel<<<(n4f + 255) / 256, 256>>>(w2, p_w2, n4f);

    // 1. xn1 = rmsnorm(x, ln1_w)  (tf32-rounded output)
    rmsnorm_kernel<<<MT, 256>>>(x, ln1_w, p_xn);

    // 2. Q, K, V
    gemm_tc<GM_NONE><<<gd_1024, 128, GEMM_SMEM>>>(p_xn, p_wq, nullptr, p_q, MT, DM, DM);
    gemm_tc<GM_NONE><<<gd_1024, 128, GEMM_SMEM>>>(p_xn, p_wk, nullptr, p_k, MT, DM, DM);
    gemm_tc<GM_NONE><<<gd_1024, 128, GEMM_SMEM>>>(p_xn, p_wv, nullptr, p_v, MT, DM, DM);

    // 3. causal flash attention (tensor cores); output tf32-rounded
    attn_tc<<<dim3(16, 16, 2), 256, ATT_SMEM_BYTES>>>(p_q, p_k, p_v, p_attn);

    // 4. x1 = x + attn @ wo.T
    gemm_tc<GM_RES><<<gd_1024, 128, GEMM_SMEM>>>(p_attn, p_wo, x, p_x1, MT, DM, DM);

    // 5. xn2 = rmsnorm(x1, ln2_w)  (tf32-rounded output)
    rmsnorm_kernel<<<MT, 256>>>(p_x1, ln2_w, p_xn);

    // 6. h = gelu(xn2 @ w1.T)  (tf32-rounded output)
    gemm_tc<GM_GELU><<<gd_ff, 128, GEMM_SMEM>>>(p_xn, p_w1, nullptr, p_h, MT, DFF, DM);

    // 7. out = x1 + h @ w2.T  (full fp32 output)
    gemm_tc<GM_RES><<<gd_1024, 128, GEMM_SMEM>>>(p_h, p_w2, p_x1, out, MT, DM, DFF);
}